// round 8
// baseline (speedup 1.0000x reference)
#include <cuda_runtime.h>
#include <math.h>

#define BB 64
#define NN 8732
#define CC 81
#define TN 64                       // anchors per conf tile
#define TPR ((NN + TN - 1) / TN)    // 137 tiles per row
#define NT (BB * TPR)               // 8768 tiles
#define NU4 (NN / 4)                // 2183 uint4 per key row

// Scratch (device globals — no runtime allocation). Every word read is written
// first in the same launch sequence: deterministic, no init kernel.
__device__ unsigned g_keys[BB * NN];     // pos -> 0, else float bits of conf_loss
__device__ unsigned char g_cnt[NT];      // per-tile positive count
__device__ float g_psum[NT];             // per-tile sum of positive conf_loss
__device__ float g_locpart[NT];          // per-tile loc loss partial

// One 64-anchor tile per 256-thread block. (unchanged — proven)
__global__ __launch_bounds__(256) void conf_kernel(const float* __restrict__ pc,
                                                   const float* __restrict__ gc,
                                                   const float* __restrict__ pl,
                                                   const float* __restrict__ gl) {
    __shared__ float sx[TN * CC];            // 20736 B raw pred_conf tile
    __shared__ float s_dot[TN];              // x[label] per anchor
    __shared__ unsigned char s_posb[TN];     // 1 if label != 0
    __shared__ float s_ps2[2];
    __shared__ int s_pc2[2];
    __shared__ float s_loc2[2];

    const int tid = threadIdx.x;
    const int lane = tid & 31;
    const int warp = tid >> 5;
    const int tile = blockIdx.x;
    const int b = blockIdx.y;
    const int n0 = tile * TN;
    const int nA = (n0 + TN <= NN) ? TN : (NN - n0);   // 64 or 28 (both %4==0)
    const int n4 = (nA * CC) >> 2;

    const size_t base = ((size_t)b * NN + n0) * CC;    // multiple of 4 floats
    const float4* p4 = (const float4*)(pc + base);
    const float4* g4 = (const float4*)(gc + base);
    for (int i = tid; i < n4; i += 256) {
        const float4 p = p4[i];
        ((float4*)sx)[i] = p;
        const float4 g = g4[i];
        if (g.x != 0.0f || g.y != 0.0f || g.z != 0.0f || g.w != 0.0f) {
            const float pv[4] = {p.x, p.y, p.z, p.w};
            const float gv[4] = {g.x, g.y, g.z, g.w};
            #pragma unroll
            for (int j = 0; j < 4; ++j) {
                if (gv[j] != 0.0f) {                   // unique writer per anchor
                    const int f = 4 * i + j;
                    const int a = f / CC;
                    const int cls = f - a * CC;
                    s_dot[a] = pv[j] * gv[j];          // = x[label] (gt value 1.0)
                    s_posb[a] = (cls != 0) ? 1 : 0;
                }
            }
        }
    }
    __syncthreads();

    if (tid < TN) {
        // thread-per-anchor: lanes access stride-81 rows -> conflict-free.
        float pv = 0.0f;
        int pc_ = 0;
        if (tid < nA) {
            const float* x = sx + tid * CC;
            float e0 = 0.0f, e1 = 0.0f, e2 = 0.0f, e3 = 0.0f;
            #pragma unroll
            for (int c = 0; c < 80; c += 4) {          // 4 indep MUFU chains
                e0 += __expf(x[c]);
                e1 += __expf(x[c + 1]);
                e2 += __expf(x[c + 2]);
                e3 += __expf(x[c + 3]);
            }
            e0 += __expf(x[80]);
            const float cl = __logf((e0 + e1) + (e2 + e3)) - s_dot[tid];
            const bool pos = s_posb[tid];
            g_keys[b * NN + n0 + tid] = pos ? 0u : __float_as_uint(cl);
            if (pos) { pv = cl; pc_ = 1; }
        }
        #pragma unroll
        for (int o = 16; o; o >>= 1) {
            pv  += __shfl_xor_sync(0xFFFFFFFFu, pv, o);
            pc_ += __shfl_xor_sync(0xFFFFFFFFu, pc_, o);
        }
        if (lane == 0) { s_ps2[warp] = pv; s_pc2[warp] = pc_; }
    } else if (tid < 128) {
        // loc partial: one anchor (float4 pair) per lane, warps 2-3.
        const int a = tid - 64;
        float ls = 0.0f;
        if (a < nA) {
            const float4* plv = (const float4*)(pl + ((size_t)b * NN + n0) * 4);
            const float4* glv = (const float4*)(gl + ((size_t)b * NN + n0) * 4);
            const float4 a4 = plv[a];
            const float4 g4v = glv[a];
            float d, ad;
            d = a4.x - g4v.x; ad = fabsf(d); if (ad > 1.0f) ls += ad - 0.5f;
            d = a4.y - g4v.y; ad = fabsf(d); if (ad > 1.0f) ls += ad - 0.5f;
            d = a4.z - g4v.z; ad = fabsf(d); if (ad > 1.0f) ls += ad - 0.5f;
            d = a4.w - g4v.w; ad = fabsf(d); if (ad > 1.0f) ls += ad - 0.5f;
        }
        #pragma unroll
        for (int o = 16; o; o >>= 1) ls += __shfl_xor_sync(0xFFFFFFFFu, ls, o);
        if (lane == 0) s_loc2[warp - 2] = ls;
    }
    __syncthreads();
    if (tid == 0) {
        const int t = b * TPR + tile;
        g_psum[t] = s_ps2[0] + s_ps2[1];
        g_cnt[t] = (unsigned char)(s_pc2[0] + s_pc2[1]);
        g_locpart[t] = s_loc2[0] + s_loc2[1];
    }
}

// One 1024-thread block per batch row. Radix select with a 13-bit FIRST pass
// (8192 bins: sign+exp+4 mantissa bits -> keys actually split), compaction of
// survivors (C small), then 13-bit + 6-bit passes and index resolution over
// candidates only. Stable (ascending-index) = jnp.argsort order throughout.
__global__ __launch_bounds__(1024) void select_kernel(float* __restrict__ out, int half) {
    const int b = blockIdx.x;
    const int tid = threadIdx.x;
    const int lane = tid & 31;
    const int warp = tid >> 5;

    __shared__ __align__(16) unsigned keys[NN];       // 34928 B
    __shared__ unsigned short cand[NN];               // 17464 B
    __shared__ int hist[8192];                        // 32768 B
    __shared__ float s_rf[32], s_rf2[32];
    __shared__ int s_ri[32], s_w[32];
    __shared__ int s_sel, s_want, s_idx, s_k, s_C;
    __shared__ float s_ps, s_ls;

    #pragma unroll
    for (int i = 0; i < 8; ++i) hist[tid + i * 1024] = 0;
    __syncthreads();

    // (1) load key row (uint4) + pass-1 histogram (key bits [19,32), 13 bits).
    const uint4* k4 = (const uint4*)(g_keys + (size_t)b * NN);
    for (int i = tid; i < 3072; i += 1024) {           // uniform 3 iterations
        uint4 v = make_uint4(0u, 0u, 0u, 0u);
        const bool ok = (i < NU4);
        if (ok) { v = k4[i]; ((uint4*)keys)[i] = v; }
        const unsigned kk[4] = {v.x, v.y, v.z, v.w};
        #pragma unroll
        for (int j = 0; j < 4; ++j) {
            const int bj = ok ? (int)(kk[j] >> 19) : -1;
            unsigned m = __match_any_sync(0xFFFFFFFFu, bj);
            if (bj >= 0 && (__ffs(m) - 1) == lane) atomicAdd(&hist[bj], __popc(m));
        }
    }

    // global positive count -> k; row pos-sum and loc-sum from tile partials.
    int c = 0;
    const uchar4* c4 = (const uchar4*)g_cnt;
    for (int i = tid; i < NT / 4; i += 1024) {
        uchar4 u = c4[i];
        c += u.x + u.y + u.z + u.w;
    }
    float ps = 0.0f, lp = 0.0f;
    for (int i = tid; i < TPR; i += 1024) {
        ps += g_psum[b * TPR + i];
        lp += g_locpart[b * TPR + i];
    }
    #pragma unroll
    for (int o = 16; o; o >>= 1) {
        c  += __shfl_xor_sync(0xFFFFFFFFu, c, o);
        ps += __shfl_xor_sync(0xFFFFFFFFu, ps, o);
        lp += __shfl_xor_sync(0xFFFFFFFFu, lp, o);
    }
    if (lane == 0) { s_ri[warp] = c; s_rf[warp] = ps; s_rf2[warp] = lp; }
    __syncthreads();
    if (tid == 0) {
        int tc = 0; float tp = 0.0f, tl = 0.0f;
        #pragma unroll
        for (int w = 0; w < 32; ++w) { tc += s_ri[w]; tp += s_rf[w]; tl += s_rf2[w]; }
        int k = 3 * tc;                  // (3.0f * num_pos) -> int32, exact
        if (k > NN - 1) k = NN - 1;
        if (k < 0) k = 0;
        s_k = k; s_ps = tp; s_ls = tl;
    }
    __syncthreads();

    int want = s_k;

    // block-wide digit pick over 8192 bins (8 consecutive bins/thread).
    #define PICK_8K()                                                             \
    {                                                                             \
        int bl[8]; int bsum = 0;                                                  \
        _Pragma("unroll")                                                         \
        for (int j = 0; j < 8; ++j) { bl[j] = hist[8 * tid + j]; bsum += bl[j]; } \
        int incl_ = bsum;                                                         \
        _Pragma("unroll")                                                         \
        for (int o = 1; o < 32; o <<= 1) {                                        \
            int t = __shfl_up_sync(0xFFFFFFFFu, incl_, o);                        \
            if (lane >= o) incl_ += t;                                            \
        }                                                                         \
        if (lane == 31) s_w[warp] = incl_;                                        \
        __syncthreads();                                                          \
        if (warp == 0) {                                                          \
            int t = s_w[lane];                                                    \
            int ti = t;                                                           \
            _Pragma("unroll")                                                     \
            for (int o = 1; o < 32; o <<= 1) {                                    \
                int u = __shfl_up_sync(0xFFFFFFFFu, ti, o);                       \
                if (lane >= o) ti += u;                                           \
            }                                                                     \
            s_w[lane] = ti - t;                                                   \
        }                                                                         \
        __syncthreads();                                                          \
        const int excl_ = s_w[warp] + incl_ - bsum;                               \
        if (want >= excl_ && want < excl_ + bsum) {                               \
            int w_ = want - excl_;                                                \
            _Pragma("unroll")                                                     \
            for (int j = 0; j < 8; ++j) {                                         \
                if (w_ < bl[j]) { s_sel = 8 * tid + j; s_want = w_; break; }      \
                w_ -= bl[j];                                                      \
            }                                                                     \
        }                                                                         \
        __syncthreads();                                                          \
    }

    // block scan of per-thread int `val` -> exclusive offset `excl`, total s_C.
    #define BLOCK_SCAN(val, excl)                                                 \
    {                                                                             \
        int incl_ = (val);                                                        \
        _Pragma("unroll")                                                         \
        for (int o = 1; o < 32; o <<= 1) {                                        \
            int t = __shfl_up_sync(0xFFFFFFFFu, incl_, o);                        \
            if (lane >= o) incl_ += t;                                            \
        }                                                                         \
        if (lane == 31) s_w[warp] = incl_;                                        \
        __syncthreads();                                                          \
        if (warp == 0) {                                                          \
            int t = s_w[lane];                                                    \
            int ti = t;                                                           \
            _Pragma("unroll")                                                     \
            for (int o = 1; o < 32; o <<= 1) {                                    \
                int u = __shfl_up_sync(0xFFFFFFFFu, ti, o);                       \
                if (lane >= o) ti += u;                                           \
            }                                                                     \
            s_w[lane] = ti - t;                                                   \
            if (lane == 31) s_C = ti;                                             \
        }                                                                         \
        __syncthreads();                                                          \
        (excl) = s_w[warp] + incl_ - (val);                                       \
    }

    PICK_8K();
    const unsigned pref1 = (unsigned)s_sel;            // top 13 bits
    want = s_want;
    __syncthreads();

    // (2) order-preserving compaction of pass-1 survivors (ascending index).
    const int lo = tid * 9;                            // 9*1024 >= NN
    const int hiE = (lo + 9 < NN) ? lo + 9 : NN;
    int cnt = 0;
    for (int n = lo; n < hiE; ++n) if ((keys[n] >> 19) == pref1) ++cnt;
    int off;
    BLOCK_SCAN(cnt, off);
    const int C = s_C;                                 // selected bin count >= 1
    for (int n = lo; n < hiE; ++n)
        if ((keys[n] >> 19) == pref1) cand[off++] = (unsigned short)n;
    const int Cpad = (C + 1023) & ~1023;
    __syncthreads();

    // (3) pass 2 over candidates: bits [6,19) (all cand share pref1).
    #pragma unroll
    for (int i = 0; i < 8; ++i) hist[tid + i * 1024] = 0;
    __syncthreads();
    for (int i = tid; i < Cpad; i += 1024) {
        const int bin = (i < C) ? (int)((keys[cand[i]] >> 6) & 8191u) : -1;
        unsigned m = __match_any_sync(0xFFFFFFFFu, bin);
        if (bin >= 0 && (__ffs(m) - 1) == lane) atomicAdd(&hist[bin], __popc(m));
    }
    __syncthreads();
    PICK_8K();
    const unsigned pref2 = (pref1 << 13) | (unsigned)s_sel;   // top 26 bits
    want = s_want;
    __syncthreads();

    // (4) pass 3 over candidates: bits [0,6), 64 bins, guarded by pref2.
    if (tid < 64) hist[tid] = 0;
    __syncthreads();
    for (int i = tid; i < Cpad; i += 1024) {
        int bin = -1;
        if (i < C) {
            const unsigned k = keys[cand[i]];
            if ((k >> 6) == pref2) bin = (int)(k & 63u);
        }
        unsigned m = __match_any_sync(0xFFFFFFFFu, bin);
        if (bin >= 0 && (__ffs(m) - 1) == lane) atomicAdd(&hist[bin], __popc(m));
    }
    __syncthreads();
    if (warp == 0) {                                   // 64-bin pick in one warp
        const int b0 = hist[2 * lane], b1 = hist[2 * lane + 1];
        const int s = b0 + b1;
        int incl_ = s;
        #pragma unroll
        for (int o = 1; o < 32; o <<= 1) {
            int t = __shfl_up_sync(0xFFFFFFFFu, incl_, o);
            if (lane >= o) incl_ += t;
        }
        const int excl_ = incl_ - s;
        if (want >= excl_ && want < excl_ + s) {
            if (want - excl_ < b0) { s_sel = 2 * lane;     s_want = want - excl_; }
            else                   { s_sel = 2 * lane + 1; s_want = want - excl_ - b0; }
        }
    }
    __syncthreads();
    const unsigned v = (pref2 << 6) | (unsigned)s_sel;        // rank-k key value
    const int r = s_want;                                     // rank among equal keys
    __syncthreads();

    // (5) resolve original index over candidates (ascending-index cand list ->
    // stable, = jnp.argsort order).
    const int clo = tid * 9;
    const int chi = (clo + 9 < C) ? clo + 9 : C;
    int cc = 0;
    for (int i = clo; i < chi; ++i) if (keys[cand[i]] == v) ++cc;
    int cex;
    BLOCK_SCAN(cc, cex);
    if (r >= cex && r < cex + cc) {
        int rr = r - cex;
        for (int i = clo; i < chi; ++i) {
            if (keys[cand[i]] == v) {
                if (rr == 0) { s_idx = (int)cand[i]; break; }
                --rr;
            }
        }
    }
    __syncthreads();
    const float thr = (float)s_idx;   // the quirk: argsort INDEX as threshold

    // (6) negative conf sum (positives are key 0, auto-excluded since thr >= 0).
    float nsum = 0.0f;
    for (int i = tid; i < NU4; i += 1024) {
        uint4 u = ((const uint4*)keys)[i];
        float f;
        f = __uint_as_float(u.x); if (f > thr) nsum += f;
        f = __uint_as_float(u.y); if (f > thr) nsum += f;
        f = __uint_as_float(u.z); if (f > thr) nsum += f;
        f = __uint_as_float(u.w); if (f > thr) nsum += f;
    }
    #pragma unroll
    for (int o = 16; o; o >>= 1) nsum += __shfl_xor_sync(0xFFFFFFFFu, nsum, o);
    if (lane == 0) s_rf[warp] = nsum;
    __syncthreads();
    if (tid == 0) {
        float t = 0.0f;
        #pragma unroll
        for (int w = 0; w < 32; ++w) t += s_rf[w];
        out[b] = s_ps + t;
        out[half + b] = s_ls;
    }
    #undef PICK_8K
    #undef BLOCK_SCAN
}

extern "C" void kernel_launch(void* const* d_in, const int* in_sizes, int n_in,
                              void* d_out, int out_size) {
    const int big_sz = BB * NN * CC;
    int ib[2] = {-1, -1}, is[2] = {-1, -1};
    int nb = 0, ns = 0;
    for (int i = 0; i < n_in; ++i) {
        if (in_sizes[i] == big_sz) { if (nb < 2) ib[nb] = i; ++nb; }
        else                       { if (ns < 2) is[ns] = i; ++ns; }
    }
    const float* pred_conf = (const float*)d_in[ib[0]];
    const float* gt_conf   = (const float*)d_in[ib[1]];
    const float* pred_loc  = (const float*)d_in[is[0]];
    const float* gt_loc    = (const float*)d_in[is[1]];
    float* out = (float*)d_out;
    const int half = out_size / 2;

    dim3 gridc(TPR, BB);
    conf_kernel<<<gridc, 256>>>(pred_conf, gt_conf, pred_loc, gt_loc);
    select_kernel<<<BB, 1024>>>(out, half);
}

// round 9
// speedup vs baseline: 1.0212x; 1.0212x over previous
#include <cuda_runtime.h>
#include <math.h>

#define BB 64
#define NN 8732
#define CC 81
#define TN 64                       // anchors per conf tile
#define TPR ((NN + TN - 1) / TN)    // 137 tiles per row
#define NT (BB * TPR)               // 8768 tiles
#define NU4 (NN / 4)                // 2183 uint4 per key row

// Scratch (device globals — no runtime allocation). Every word read is written
// first in the same launch sequence: deterministic, no init kernel.
__device__ unsigned g_keys[BB * NN];     // pos -> 0, else float bits of conf_loss
__device__ unsigned char g_cnt[NT];      // per-tile positive count
__device__ float g_psum[NT];             // per-tile sum of positive conf_loss
__device__ float g_locpart[NT];          // per-tile loc loss partial

// One 64-anchor tile per 256-thread block.
// Phase 1: stage pred_conf tile (float4) + one-hot label extraction (gt_conf
//          has EXACTLY one nonzero per anchor -> unique writer, no atomics).
// Phase 2: warps 0-1: Σexp classes [0,40) per anchor; warps 2-3: Σexp classes
//          [40,81) -> s_half; warps 4-5: loc partial. All stride-81 accesses
//          are bank-conflict-free (17 coprime to 32).
__global__ __launch_bounds__(256) void conf_kernel(const float* __restrict__ pc,
                                                   const float* __restrict__ gc,
                                                   const float* __restrict__ pl,
                                                   const float* __restrict__ gl) {
    __shared__ float sx[TN * CC];            // 20736 B raw pred_conf tile
    __shared__ float s_dot[TN];              // x[label] per anchor
    __shared__ unsigned char s_posb[TN];     // 1 if label != 0
    __shared__ float s_half[TN];             // Σexp classes [40,81)
    __shared__ float s_ps2[2];
    __shared__ int s_pc2[2];
    __shared__ float s_loc2[2];

    const int tid = threadIdx.x;
    const int lane = tid & 31;
    const int warp = tid >> 5;
    const int tile = blockIdx.x;
    const int b = blockIdx.y;
    const int n0 = tile * TN;
    const int nA = (n0 + TN <= NN) ? TN : (NN - n0);   // 64 or 28 (both %4==0)
    const int n4 = (nA * CC) >> 2;

    const size_t base = ((size_t)b * NN + n0) * CC;    // multiple of 4 floats
    const float4* p4 = (const float4*)(pc + base);
    const float4* g4 = (const float4*)(gc + base);
    for (int i = tid; i < n4; i += 256) {
        const float4 p = p4[i];
        ((float4*)sx)[i] = p;
        const float4 g = g4[i];
        if (g.x != 0.0f || g.y != 0.0f || g.z != 0.0f || g.w != 0.0f) {
            const float pv[4] = {p.x, p.y, p.z, p.w};
            const float gv[4] = {g.x, g.y, g.z, g.w};
            #pragma unroll
            for (int j = 0; j < 4; ++j) {
                if (gv[j] != 0.0f) {                   // unique writer per anchor
                    const int f = 4 * i + j;
                    const int a = f / CC;
                    const int cls = f - a * CC;
                    s_dot[a] = pv[j] * gv[j];          // = x[label] (gt value 1.0)
                    s_posb[a] = (cls != 0) ? 1 : 0;
                }
            }
        }
    }
    __syncthreads();

    float myE = 0.0f;
    if (tid < 64) {
        // classes [0,40) for anchor tid
        if (tid < nA) {
            const float* x = sx + tid * CC;
            float e0 = 0.0f, e1 = 0.0f, e2 = 0.0f, e3 = 0.0f;
            #pragma unroll
            for (int c = 0; c < 40; c += 4) {
                e0 += __expf(x[c]);     e1 += __expf(x[c + 1]);
                e2 += __expf(x[c + 2]); e3 += __expf(x[c + 3]);
            }
            myE = (e0 + e1) + (e2 + e3);
        }
    } else if (tid < 128) {
        // classes [40,81) for anchor tid-64
        const int a = tid - 64;
        if (a < nA) {
            const float* x = sx + a * CC + 40;
            float e0 = 0.0f, e1 = 0.0f, e2 = 0.0f, e3 = 0.0f;
            #pragma unroll
            for (int c = 0; c < 40; c += 4) {
                e0 += __expf(x[c]);     e1 += __expf(x[c + 1]);
                e2 += __expf(x[c + 2]); e3 += __expf(x[c + 3]);
            }
            e0 += __expf(x[40]);                       // class 80
            s_half[a] = (e0 + e1) + (e2 + e3);
        }
    } else if (tid < 192) {
        // loc partial: one anchor (float4 pair) per lane, warps 4-5.
        const int a = tid - 128;
        float ls = 0.0f;
        if (a < nA) {
            const float4* plv = (const float4*)(pl + ((size_t)b * NN + n0) * 4);
            const float4* glv = (const float4*)(gl + ((size_t)b * NN + n0) * 4);
            const float4 a4 = plv[a];
            const float4 g4v = glv[a];
            float d, ad;
            d = a4.x - g4v.x; ad = fabsf(d); if (ad > 1.0f) ls += ad - 0.5f;
            d = a4.y - g4v.y; ad = fabsf(d); if (ad > 1.0f) ls += ad - 0.5f;
            d = a4.z - g4v.z; ad = fabsf(d); if (ad > 1.0f) ls += ad - 0.5f;
            d = a4.w - g4v.w; ad = fabsf(d); if (ad > 1.0f) ls += ad - 0.5f;
        }
        #pragma unroll
        for (int o = 16; o; o >>= 1) ls += __shfl_xor_sync(0xFFFFFFFFu, ls, o);
        if (lane == 0) s_loc2[warp - 4] = ls;
    }
    __syncthreads();

    if (tid < 64) {
        float pv = 0.0f;
        int pc_ = 0;
        if (tid < nA) {
            const float e = myE + s_half[tid];
            const float cl = __logf(e) - s_dot[tid];   // lse - x[label] > 0
            const bool pos = s_posb[tid];
            g_keys[b * NN + n0 + tid] = pos ? 0u : __float_as_uint(cl);
            if (pos) { pv = cl; pc_ = 1; }
        }
        #pragma unroll
        for (int o = 16; o; o >>= 1) {
            pv  += __shfl_xor_sync(0xFFFFFFFFu, pv, o);
            pc_ += __shfl_xor_sync(0xFFFFFFFFu, pc_, o);
        }
        if (lane == 0) { s_ps2[warp] = pv; s_pc2[warp] = pc_; }
    }
    __syncthreads();
    if (tid == 0) {
        const int t = b * TPR + tile;
        g_psum[t] = s_ps2[0] + s_ps2[1];
        g_cnt[t] = (unsigned char)(s_pc2[0] + s_pc2[1]);
        g_locpart[t] = s_loc2[0] + s_loc2[1];
    }
}

// One 1024-thread block per batch row. 3-pass (11/11/10 bit) radix rank-k
// select; pass 1 fused into the load. Passes 2/3 are SKIPPED when the selected
// bin already holds a single key (resolve then matches the prefix — provably
// identical result). negsum sweep is skipped when thr >= rowmax (exact).
__global__ __launch_bounds__(1024) void select_kernel(float* __restrict__ out, int half) {
    const int b = blockIdx.x;
    const int tid = threadIdx.x;
    const int lane = tid & 31;
    const int warp = tid >> 5;

    __shared__ __align__(16) unsigned keys[NN];   // 34928 B
    __shared__ int hist[2048];
    __shared__ float s_rf[32], s_rf2[32];
    __shared__ int s_ri[32], s_w[32];
    __shared__ unsigned s_ru[32];
    __shared__ int s_sel, s_want, s_idx, s_k, s_selcnt;
    __shared__ float s_ps, s_ls;
    __shared__ unsigned s_rmax;

    hist[tid] = 0; hist[tid + 1024] = 0;
    __syncthreads();

    // (1) load key row (uint4) + pass-1 histogram (key bits [21,32)) + rowmax.
    const uint4* k4 = (const uint4*)(g_keys + (size_t)b * NN);
    unsigned um = 0u;
    for (int i = tid; i < 3072; i += 1024) {           // uniform 3 iterations
        uint4 v = make_uint4(0u, 0u, 0u, 0u);
        const bool ok = (i < NU4);
        if (ok) { v = k4[i]; ((uint4*)keys)[i] = v; }
        um = max(um, max(max(v.x, v.y), max(v.z, v.w)));
        const unsigned kk[4] = {v.x, v.y, v.z, v.w};
        #pragma unroll
        for (int j = 0; j < 4; ++j) {
            const int bj = ok ? (int)(kk[j] >> 21) : -1;
            unsigned m = __match_any_sync(0xFFFFFFFFu, bj);
            if (bj >= 0 && (__ffs(m) - 1) == lane) atomicAdd(&hist[bj], __popc(m));
        }
    }

    // global positive count -> k; row pos-sum and loc-sum from tile partials.
    int c = 0;
    const uchar4* c4 = (const uchar4*)g_cnt;
    for (int i = tid; i < NT / 4; i += 1024) {
        uchar4 u = c4[i];
        c += u.x + u.y + u.z + u.w;
    }
    float ps = 0.0f, lp = 0.0f;
    for (int i = tid; i < TPR; i += 1024) {
        ps += g_psum[b * TPR + i];
        lp += g_locpart[b * TPR + i];
    }
    #pragma unroll
    for (int o = 16; o; o >>= 1) {
        c  += __shfl_xor_sync(0xFFFFFFFFu, c, o);
        ps += __shfl_xor_sync(0xFFFFFFFFu, ps, o);
        lp += __shfl_xor_sync(0xFFFFFFFFu, lp, o);
        um  = max(um, __shfl_xor_sync(0xFFFFFFFFu, um, o));
    }
    if (lane == 0) { s_ri[warp] = c; s_rf[warp] = ps; s_rf2[warp] = lp; s_ru[warp] = um; }
    __syncthreads();
    if (tid == 0) {
        int tc = 0; float tp = 0.0f, tl = 0.0f; unsigned tm = 0u;
        #pragma unroll
        for (int w = 0; w < 32; ++w) {
            tc += s_ri[w]; tp += s_rf[w]; tl += s_rf2[w]; tm = max(tm, s_ru[w]);
        }
        int k = 3 * tc;                  // (3.0f * num_pos) -> int32, exact
        if (k > NN - 1) k = NN - 1;
        if (k < 0) k = 0;
        s_k = k; s_ps = tp; s_ls = tl; s_rmax = tm;
    }
    __syncthreads();

    int want = s_k;

    // block-wide digit pick over 2048 bins (2 bins/thread); sets
    // s_sel/s_want/s_selcnt (count of the selected bin).
    #define PICK_DIGIT()                                                          \
    {                                                                             \
        const int b0 = hist[2 * tid], b1 = hist[2 * tid + 1];                     \
        const int s = b0 + b1;                                                    \
        int incl = s;                                                             \
        _Pragma("unroll")                                                         \
        for (int o = 1; o < 32; o <<= 1) {                                        \
            int t = __shfl_up_sync(0xFFFFFFFFu, incl, o);                         \
            if (lane >= o) incl += t;                                             \
        }                                                                         \
        if (lane == 31) s_w[warp] = incl;                                         \
        __syncthreads();                                                          \
        if (warp == 0) {                                                          \
            int t = s_w[lane];                                                    \
            int ti = t;                                                           \
            _Pragma("unroll")                                                     \
            for (int o = 1; o < 32; o <<= 1) {                                    \
                int u = __shfl_up_sync(0xFFFFFFFFu, ti, o);                       \
                if (lane >= o) ti += u;                                           \
            }                                                                     \
            s_w[lane] = ti - t;                                                   \
        }                                                                         \
        __syncthreads();                                                          \
        const int excl = s_w[warp] + incl - s;                                    \
        if (want >= excl && want < excl + s) {                                    \
            if (want - excl < b0) { s_sel = 2 * tid; s_want = want - excl; s_selcnt = b0; } \
            else { s_sel = 2 * tid + 1; s_want = want - excl - b0; s_selcnt = b1; } \
        }                                                                         \
        __syncthreads();                                                          \
    }

    PICK_DIGIT();
    unsigned PREF = (unsigned)s_sel;                   // top 11 bits
    int SH = 21;
    want = s_want;
    int selcnt = s_selcnt;
    __syncthreads();

    if (selcnt > 1) {
        // pass 2: bits [10,21) — uint4 sweep.
        hist[tid] = 0; hist[tid + 1024] = 0;
        __syncthreads();
        for (int i = tid; i < 3072; i += 1024) {
            uint4 v = make_uint4(0xFFFFFFFFu, 0xFFFFFFFFu, 0xFFFFFFFFu, 0xFFFFFFFFu);
            if (i < NU4) v = ((const uint4*)keys)[i];
            const unsigned kk[4] = {v.x, v.y, v.z, v.w};
            #pragma unroll
            for (int j = 0; j < 4; ++j) {
                const int bin = ((kk[j] >> 21) == PREF) ? (int)((kk[j] >> 10) & 2047) : -1;
                unsigned m = __match_any_sync(0xFFFFFFFFu, bin);
                if (bin >= 0 && (__ffs(m) - 1) == lane) atomicAdd(&hist[bin], __popc(m));
            }
        }
        __syncthreads();
        PICK_DIGIT();
        PREF = (PREF << 11) | (unsigned)s_sel;         // top 22 bits
        SH = 10;
        want = s_want;
        selcnt = s_selcnt;
        __syncthreads();

        if (selcnt > 1) {
            // pass 3: bits [0,10) — uint4 sweep.
            hist[tid] = 0; hist[tid + 1024] = 0;
            __syncthreads();
            for (int i = tid; i < 3072; i += 1024) {
                uint4 v = make_uint4(0xFFFFFFFFu, 0xFFFFFFFFu, 0xFFFFFFFFu, 0xFFFFFFFFu);
                if (i < NU4) v = ((const uint4*)keys)[i];
                const unsigned kk[4] = {v.x, v.y, v.z, v.w};
                #pragma unroll
                for (int j = 0; j < 4; ++j) {
                    const int bin = ((kk[j] >> 10) == PREF) ? (int)(kk[j] & 1023) : -1;
                    unsigned m = __match_any_sync(0xFFFFFFFFu, bin);
                    if (bin >= 0 && (__ffs(m) - 1) == lane) atomicAdd(&hist[bin], __popc(m));
                }
            }
            __syncthreads();
            PICK_DIGIT();
            PREF = (PREF << 10) | (unsigned)s_sel;     // full 32-bit key
            SH = 0;
            want = s_want;
            __syncthreads();
        }
    }
    const int r = want;                                // rank among prefix-equal keys

    // resolve original index (stable ascending = jnp.argsort) via block scan
    // over contiguous per-thread ranges; match on the resolved prefix.
    const int lo = tid * 9;                            // 9*1024 >= NN
    const int hiE = (lo + 9 < NN) ? lo + 9 : NN;
    int cnt = 0;
    for (int n = lo; n < hiE; ++n) if ((keys[n] >> SH) == PREF) ++cnt;
    int incl = cnt;
    #pragma unroll
    for (int o = 1; o < 32; o <<= 1) {
        int t = __shfl_up_sync(0xFFFFFFFFu, incl, o);
        if (lane >= o) incl += t;
    }
    if (lane == 31) s_w[warp] = incl;
    __syncthreads();
    if (warp == 0) {
        int t = s_w[lane];
        int ti = t;
        #pragma unroll
        for (int o = 1; o < 32; o <<= 1) {
            int u = __shfl_up_sync(0xFFFFFFFFu, ti, o);
            if (lane >= o) ti += u;
        }
        s_w[lane] = ti - t;
    }
    __syncthreads();
    {
        const int excl = s_w[warp] + incl - cnt;
        if (r >= excl && r < excl + cnt) {
            int rr = r - excl;
            for (int n = lo; n < hiE; ++n) {
                if ((keys[n] >> SH) == PREF) {
                    if (rr == 0) { s_idx = n; break; }
                    --rr;
                }
            }
        }
    }
    __syncthreads();
    const float thr = (float)s_idx;   // the quirk: argsort INDEX as threshold

    // negsum: skipped when no key can exceed thr (exact, since all keys are
    // nonneg floats and uint max == float max for them).
    float nsum = 0.0f;
    if (__uint_as_float(s_rmax) > thr) {
        for (int i = tid; i < NU4; i += 1024) {
            uint4 u = ((const uint4*)keys)[i];
            float f;
            f = __uint_as_float(u.x); if (f > thr) nsum += f;
            f = __uint_as_float(u.y); if (f > thr) nsum += f;
            f = __uint_as_float(u.z); if (f > thr) nsum += f;
            f = __uint_as_float(u.w); if (f > thr) nsum += f;
        }
    }
    #pragma unroll
    for (int o = 16; o; o >>= 1) nsum += __shfl_xor_sync(0xFFFFFFFFu, nsum, o);
    if (lane == 0) s_rf[warp] = nsum;
    __syncthreads();
    if (tid == 0) {
        float t = 0.0f;
        #pragma unroll
        for (int w = 0; w < 32; ++w) t += s_rf[w];
        out[b] = s_ps + t;
        out[half + b] = s_ls;
    }
    #undef PICK_DIGIT
}

extern "C" void kernel_launch(void* const* d_in, const int* in_sizes, int n_in,
                              void* d_out, int out_size) {
    const int big_sz = BB * NN * CC;
    int ib[2] = {-1, -1}, is[2] = {-1, -1};
    int nb = 0, ns = 0;
    for (int i = 0; i < n_in; ++i) {
        if (in_sizes[i] == big_sz) { if (nb < 2) ib[nb] = i; ++nb; }
        else                       { if (ns < 2) is[ns] = i; ++ns; }
    }
    const float* pred_conf = (const float*)d_in[ib[0]];
    const float* gt_conf   = (const float*)d_in[ib[1]];
    const float* pred_loc  = (const float*)d_in[is[0]];
    const float* gt_loc    = (const float*)d_in[is[1]];
    float* out = (float*)d_out;
    const int half = out_size / 2;

    dim3 gridc(TPR, BB);
    conf_kernel<<<gridc, 256>>>(pred_conf, gt_conf, pred_loc, gt_loc);
    select_kernel<<<BB, 1024>>>(out, half);
}

// round 10
// speedup vs baseline: 1.0726x; 1.0504x over previous
#include <cuda_runtime.h>
#include <math.h>

#define BB 64
#define NN 8732
#define CC 81
#define TN 64                       // anchors per conf tile
#define TPR ((NN + TN - 1) / TN)    // 137 tiles per row
#define NT (BB * TPR)               // 8768 tiles
#define NU4 (NN / 4)                // 2183 uint4 per key row

#define KEYS_BYTES 34944            // NN*4 = 34928, padded to 16
#define NBINS 16384
#define SEL_SMEM (KEYS_BYTES + NBINS * 4)   // 100480 B dynamic smem

// Scratch (device globals — no runtime allocation). Every word read is written
// first in the same launch sequence: deterministic, no init kernel.
__device__ unsigned g_keys[BB * NN];     // pos -> 0, else float bits of conf_loss
__device__ unsigned char g_cnt[NT];      // per-tile positive count
__device__ float g_psum[NT];             // per-tile sum of positive conf_loss
__device__ float g_locpart[NT];          // per-tile loc loss partial

// One 64-anchor tile per 256-thread block. (unchanged — proven)
__global__ __launch_bounds__(256) void conf_kernel(const float* __restrict__ pc,
                                                   const float* __restrict__ gc,
                                                   const float* __restrict__ pl,
                                                   const float* __restrict__ gl) {
    __shared__ float sx[TN * CC];            // 20736 B raw pred_conf tile
    __shared__ float s_dot[TN];              // x[label] per anchor
    __shared__ unsigned char s_posb[TN];     // 1 if label != 0
    __shared__ float s_half[TN];             // Σexp classes [40,81)
    __shared__ float s_ps2[2];
    __shared__ int s_pc2[2];
    __shared__ float s_loc2[2];

    const int tid = threadIdx.x;
    const int lane = tid & 31;
    const int warp = tid >> 5;
    const int tile = blockIdx.x;
    const int b = blockIdx.y;
    const int n0 = tile * TN;
    const int nA = (n0 + TN <= NN) ? TN : (NN - n0);   // 64 or 28 (both %4==0)
    const int n4 = (nA * CC) >> 2;

    const size_t base = ((size_t)b * NN + n0) * CC;    // multiple of 4 floats
    const float4* p4 = (const float4*)(pc + base);
    const float4* g4 = (const float4*)(gc + base);
    for (int i = tid; i < n4; i += 256) {
        const float4 p = p4[i];
        ((float4*)sx)[i] = p;
        const float4 g = g4[i];
        if (g.x != 0.0f || g.y != 0.0f || g.z != 0.0f || g.w != 0.0f) {
            const float pv[4] = {p.x, p.y, p.z, p.w};
            const float gv[4] = {g.x, g.y, g.z, g.w};
            #pragma unroll
            for (int j = 0; j < 4; ++j) {
                if (gv[j] != 0.0f) {                   // unique writer per anchor
                    const int f = 4 * i + j;
                    const int a = f / CC;
                    const int cls = f - a * CC;
                    s_dot[a] = pv[j] * gv[j];          // = x[label] (gt value 1.0)
                    s_posb[a] = (cls != 0) ? 1 : 0;
                }
            }
        }
    }
    __syncthreads();

    float myE = 0.0f;
    if (tid < 64) {
        if (tid < nA) {
            const float* x = sx + tid * CC;
            float e0 = 0.0f, e1 = 0.0f, e2 = 0.0f, e3 = 0.0f;
            #pragma unroll
            for (int c = 0; c < 40; c += 4) {
                e0 += __expf(x[c]);     e1 += __expf(x[c + 1]);
                e2 += __expf(x[c + 2]); e3 += __expf(x[c + 3]);
            }
            myE = (e0 + e1) + (e2 + e3);
        }
    } else if (tid < 128) {
        const int a = tid - 64;
        if (a < nA) {
            const float* x = sx + a * CC + 40;
            float e0 = 0.0f, e1 = 0.0f, e2 = 0.0f, e3 = 0.0f;
            #pragma unroll
            for (int c = 0; c < 40; c += 4) {
                e0 += __expf(x[c]);     e1 += __expf(x[c + 1]);
                e2 += __expf(x[c + 2]); e3 += __expf(x[c + 3]);
            }
            e0 += __expf(x[40]);                       // class 80
            s_half[a] = (e0 + e1) + (e2 + e3);
        }
    } else if (tid < 192) {
        const int a = tid - 128;
        float ls = 0.0f;
        if (a < nA) {
            const float4* plv = (const float4*)(pl + ((size_t)b * NN + n0) * 4);
            const float4* glv = (const float4*)(gl + ((size_t)b * NN + n0) * 4);
            const float4 a4 = plv[a];
            const float4 g4v = glv[a];
            float d, ad;
            d = a4.x - g4v.x; ad = fabsf(d); if (ad > 1.0f) ls += ad - 0.5f;
            d = a4.y - g4v.y; ad = fabsf(d); if (ad > 1.0f) ls += ad - 0.5f;
            d = a4.z - g4v.z; ad = fabsf(d); if (ad > 1.0f) ls += ad - 0.5f;
            d = a4.w - g4v.w; ad = fabsf(d); if (ad > 1.0f) ls += ad - 0.5f;
        }
        #pragma unroll
        for (int o = 16; o; o >>= 1) ls += __shfl_xor_sync(0xFFFFFFFFu, ls, o);
        if (lane == 0) s_loc2[warp - 4] = ls;
    }
    __syncthreads();

    if (tid < 64) {
        float pv = 0.0f;
        int pc_ = 0;
        if (tid < nA) {
            const float e = myE + s_half[tid];
            const float cl = __logf(e) - s_dot[tid];   // lse - x[label] > 0
            const bool pos = s_posb[tid];
            g_keys[b * NN + n0 + tid] = pos ? 0u : __float_as_uint(cl);
            if (pos) { pv = cl; pc_ = 1; }
        }
        #pragma unroll
        for (int o = 16; o; o >>= 1) {
            pv  += __shfl_xor_sync(0xFFFFFFFFu, pv, o);
            pc_ += __shfl_xor_sync(0xFFFFFFFFu, pc_, o);
        }
        if (lane == 0) { s_ps2[warp] = pv; s_pc2[warp] = pc_; }
    }
    __syncthreads();
    if (tid == 0) {
        const int t = b * TPR + tile;
        g_psum[t] = s_ps2[0] + s_ps2[1];
        g_cnt[t] = (unsigned char)(s_pc2[0] + s_pc2[1]);
        g_locpart[t] = s_loc2[0] + s_loc2[1];
    }
}

// One 1024-thread block per batch row. ADAPTIVE-RANGE rank-k select:
// zero-group (positives) removed analytically; remaining keys binned by
// (key - cLo) >> sh over 16384 bins sized to the occupied bit range
// (monotone -> exact radix-select). Realistic data: 2 histogram rounds,
// spread bins (raw atomics, no match_any). Stable argsort-index resolve.
__global__ __launch_bounds__(1024) void select_kernel(float* __restrict__ out, int half) {
    extern __shared__ __align__(16) unsigned char dsm[];
    unsigned* keys = (unsigned*)dsm;                  // NN uints
    int* hist = (int*)(dsm + KEYS_BYTES);             // 16384 ints

    __shared__ float s_rf[32], s_rf2[32];
    __shared__ int s_ri[32], s_zi[32], s_w[32];
    __shared__ unsigned s_rmx[32], s_rmn[32];
    __shared__ int s_sel, s_want, s_idx, s_k, s_zc;
    __shared__ float s_ps, s_ls;
    __shared__ unsigned s_max, s_min;

    const int b = blockIdx.x;
    const int tid = threadIdx.x;
    const int lane = tid & 31;
    const int warp = tid >> 5;

    // (1) load keys + rowstats (no atomics): max, min-of-nonzero, zero count.
    const uint4* k4 = (const uint4*)(g_keys + (size_t)b * NN);
    unsigned umax = 0u, umin = 0xFFFFFFFFu;
    int zc = 0;
    for (int i = tid; i < NU4; i += 1024) {
        uint4 v = k4[i];
        ((uint4*)keys)[i] = v;
        #define ST(x) { if (x) { umax = max(umax, (x)); umin = min(umin, (x)); } else ++zc; }
        ST(v.x) ST(v.y) ST(v.z) ST(v.w)
        #undef ST
    }
    // global positive count -> k; row pos-sum and loc-sum from tile partials.
    int c = 0;
    const uchar4* c4 = (const uchar4*)g_cnt;
    for (int i = tid; i < NT / 4; i += 1024) {
        uchar4 u = c4[i];
        c += u.x + u.y + u.z + u.w;
    }
    float ps = 0.0f, lp = 0.0f;
    for (int i = tid; i < TPR; i += 1024) {
        ps += g_psum[b * TPR + i];
        lp += g_locpart[b * TPR + i];
    }
    #pragma unroll
    for (int o = 16; o; o >>= 1) {
        c    += __shfl_xor_sync(0xFFFFFFFFu, c, o);
        zc   += __shfl_xor_sync(0xFFFFFFFFu, zc, o);
        ps   += __shfl_xor_sync(0xFFFFFFFFu, ps, o);
        lp   += __shfl_xor_sync(0xFFFFFFFFu, lp, o);
        umax  = max(umax, __shfl_xor_sync(0xFFFFFFFFu, umax, o));
        umin  = min(umin, __shfl_xor_sync(0xFFFFFFFFu, umin, o));
    }
    if (lane == 0) {
        s_ri[warp] = c; s_zi[warp] = zc; s_rf[warp] = ps; s_rf2[warp] = lp;
        s_rmx[warp] = umax; s_rmn[warp] = umin;
    }
    __syncthreads();
    if (tid == 0) {
        int tc = 0, tz = 0; float tp = 0.0f, tl = 0.0f;
        unsigned tm = 0u, tn = 0xFFFFFFFFu;
        #pragma unroll
        for (int w = 0; w < 32; ++w) {
            tc += s_ri[w]; tz += s_zi[w]; tp += s_rf[w]; tl += s_rf2[w];
            tm = max(tm, s_rmx[w]); tn = min(tn, s_rmn[w]);
        }
        int k = 3 * tc;                  // (3.0f * num_pos) -> int32, exact
        if (k > NN - 1) k = NN - 1;
        if (k < 0) k = 0;
        s_k = k; s_ps = tp; s_ls = tl; s_zc = tz; s_max = tm; s_min = tn;
    }
    __syncthreads();

    // (2) rank-k: zero group first (keys==0 sort before all nonzero, stable).
    int want = s_k;
    unsigned target = 0u;
    int r = 0;
    if (want < s_zc) {
        target = 0u; r = want;           // k-th element is a zero key
    } else {
        want -= s_zc;
        unsigned cLo = s_min, cHi = s_max;
        while (true) {
            const unsigned range = cHi - cLo;
            if (range == 0u) { target = cLo; r = want; break; }
            const int bits = 32 - __clz(range);
            const int sh = (bits > 14) ? (bits - 14) : 0;
            #pragma unroll
            for (int q = 0; q < 4; ++q)
                ((int4*)hist)[tid + q * 1024] = make_int4(0, 0, 0, 0);
            __syncthreads();
            for (int i = tid; i < NU4; i += 1024) {
                uint4 v = ((const uint4*)keys)[i];
                #define HB(x) if ((x) >= cLo && (x) <= cHi) atomicAdd(&hist[((x) - cLo) >> sh], 1);
                HB(v.x) HB(v.y) HB(v.z) HB(v.w)
                #undef HB
            }
            __syncthreads();
            // pick bin over 16384 bins (16/thread)
            {
                int bl[16]; int bsum = 0;
                #pragma unroll
                for (int j = 0; j < 16; ++j) { bl[j] = hist[16 * tid + j]; bsum += bl[j]; }
                int incl = bsum;
                #pragma unroll
                for (int o = 1; o < 32; o <<= 1) {
                    int t = __shfl_up_sync(0xFFFFFFFFu, incl, o);
                    if (lane >= o) incl += t;
                }
                if (lane == 31) s_w[warp] = incl;
                __syncthreads();
                if (warp == 0) {
                    int t = s_w[lane];
                    int ti = t;
                    #pragma unroll
                    for (int o = 1; o < 32; o <<= 1) {
                        int u = __shfl_up_sync(0xFFFFFFFFu, ti, o);
                        if (lane >= o) ti += u;
                    }
                    s_w[lane] = ti - t;
                }
                __syncthreads();
                const int excl = s_w[warp] + incl - bsum;
                if (want >= excl && want < excl + bsum) {
                    int w_ = want - excl;
                    #pragma unroll
                    for (int j = 0; j < 16; ++j) {
                        if (w_ < bl[j]) { s_sel = 16 * tid + j; s_want = w_; break; }
                        w_ -= bl[j];
                    }
                }
                __syncthreads();
            }
            const int B = s_sel;
            want = s_want;
            if (sh == 0) { target = cLo + (unsigned)B; r = want; break; }
            cLo += ((unsigned)B) << sh;
            {
                const unsigned span = (1u << sh) - 1u;
                unsigned nHi = cLo + span;
                if (nHi > cHi || nHi < cLo) nHi = cHi;   // clamp (incl. wrap)
                cHi = nHi;
            }
        }
    }

    // (3) resolve stable argsort index: r-th (ascending index) key == target.
    const int lo = tid * 9;                            // 9*1024 >= NN
    const int hiE = (lo + 9 < NN) ? lo + 9 : NN;
    int cnt = 0;
    for (int n = lo; n < hiE; ++n) if (keys[n] == target) ++cnt;
    int incl = cnt;
    #pragma unroll
    for (int o = 1; o < 32; o <<= 1) {
        int t = __shfl_up_sync(0xFFFFFFFFu, incl, o);
        if (lane >= o) incl += t;
    }
    if (lane == 31) s_w[warp] = incl;
    __syncthreads();
    if (warp == 0) {
        int t = s_w[lane];
        int ti = t;
        #pragma unroll
        for (int o = 1; o < 32; o <<= 1) {
            int u = __shfl_up_sync(0xFFFFFFFFu, ti, o);
            if (lane >= o) ti += u;
        }
        s_w[lane] = ti - t;
    }
    __syncthreads();
    {
        const int excl = s_w[warp] + incl - cnt;
        if (r >= excl && r < excl + cnt) {
            int rr = r - excl;
            for (int n = lo; n < hiE; ++n) {
                if (keys[n] == target) {
                    if (rr == 0) { s_idx = n; break; }
                    --rr;
                }
            }
        }
    }
    __syncthreads();
    const float thr = (float)s_idx;   // the quirk: argsort INDEX as threshold

    // (4) negsum: skipped when no key can exceed thr (exact — keys are
    // nonneg floats, uint max == float max).
    float nsum = 0.0f;
    if (__uint_as_float(s_max) > thr) {
        for (int i = tid; i < NU4; i += 1024) {
            uint4 u = ((const uint4*)keys)[i];
            float f;
            f = __uint_as_float(u.x); if (f > thr) nsum += f;
            f = __uint_as_float(u.y); if (f > thr) nsum += f;
            f = __uint_as_float(u.z); if (f > thr) nsum += f;
            f = __uint_as_float(u.w); if (f > thr) nsum += f;
        }
    }
    #pragma unroll
    for (int o = 16; o; o >>= 1) nsum += __shfl_xor_sync(0xFFFFFFFFu, nsum, o);
    if (lane == 0) s_rf[warp] = nsum;
    __syncthreads();
    if (tid == 0) {
        float t = 0.0f;
        #pragma unroll
        for (int w = 0; w < 32; ++w) t += s_rf[w];
        out[b] = s_ps + t;
        out[half + b] = s_ls;
    }
}

extern "C" void kernel_launch(void* const* d_in, const int* in_sizes, int n_in,
                              void* d_out, int out_size) {
    const int big_sz = BB * NN * CC;
    int ib[2] = {-1, -1}, is[2] = {-1, -1};
    int nb = 0, ns = 0;
    for (int i = 0; i < n_in; ++i) {
        if (in_sizes[i] == big_sz) { if (nb < 2) ib[nb] = i; ++nb; }
        else                       { if (ns < 2) is[ns] = i; ++ns; }
    }
    const float* pred_conf = (const float*)d_in[ib[0]];
    const float* gt_conf   = (const float*)d_in[ib[1]];
    const float* pred_loc  = (const float*)d_in[is[0]];
    const float* gt_loc    = (const float*)d_in[is[1]];
    float* out = (float*)d_out;
    const int half = out_size / 2;

    cudaFuncSetAttribute(select_kernel,
                         cudaFuncAttributeMaxDynamicSharedMemorySize, SEL_SMEM);

    dim3 gridc(TPR, BB);
    conf_kernel<<<gridc, 256>>>(pred_conf, gt_conf, pred_loc, gt_loc);
    select_kernel<<<BB, 1024, SEL_SMEM>>>(out, half);
}